// round 13
// baseline (speedup 1.0000x reference)
#include <cuda_runtime.h>
#include <cuda_bf16.h>

#define BATCH 16
#define DIM   48
#define HID   16
#define CH    8
#define HH    256
#define WW    256
#define HW    (HH*WW)          // 65536
#define TILE  32
#define HT    34               // tile + halo
#define PITCH 35               // padded smem row pitch (conflict-free)

typedef unsigned long long u64;

__constant__ float cW1[DIM*HID];
__constant__ float cB1[HID];
__constant__ float cGamma[CH];
__constant__ float cBeta[CH];
__constant__ float cDW[CH*9];
__constant__ float cDWB[CH];
__constant__ float cPW[CH*CH];
__constant__ float cPWB[CH];
__constant__ float cW2[CH*DIM];
__constant__ float cB2[DIM];

// scratch: front-half outputs (allowed: __device__ global arrays)
__device__ float g_x1[(size_t)BATCH*HW*CH];   // token-major  [b*HW+p][8]
__device__ float g_n [(size_t)BATCH*CH*HW];   // chan-planar  [(b*8+c)*HW+p]

// ---------------- f32x2 packed primitives ----------------
#define F2U(x) __builtin_bit_cast(unsigned int, (x))
#define DUPC(x) ((((u64)F2U(x)) << 32) | (u64)F2U(x))

__device__ __forceinline__ u64 f2fma(u64 a, u64 b, u64 c) {
    u64 d; asm("fma.rn.f32x2 %0,%1,%2,%3;" : "=l"(d) : "l"(a), "l"(b), "l"(c)); return d;
}
__device__ __forceinline__ u64 f2mul(u64 a, u64 b) {
    u64 d; asm("mul.rn.f32x2 %0,%1,%2;" : "=l"(d) : "l"(a), "l"(b)); return d;
}
__device__ __forceinline__ u64 f2add(u64 a, u64 b) {
    u64 d; asm("add.rn.f32x2 %0,%1,%2;" : "=l"(d) : "l"(a), "l"(b)); return d;
}
__device__ __forceinline__ u64 pk(float lo, float hi) {
    u64 r; asm("mov.b64 %0,{%1,%2};" : "=l"(r) : "f"(lo), "f"(hi)); return r;
}
__device__ __forceinline__ void upk(float& lo, float& hi, u64 v) {
    asm("mov.b64 {%0,%1},%2;" : "=f"(lo), "=f"(hi) : "l"(v));
}

// ---------------- packed MUFU-free exact GELU (verified in R7) ----------------
__device__ __forceinline__ u64 gelu2(u64 u2) {
    u64 t2 = f2mul(f2mul(u2, u2), DUPC(-0.72134752044f));   // -x^2*log2(e), x=|u|/sqrt2
    u64 fv = f2add(t2, DUPC(12582912.0f));                  // round to nearest int
    u64 fm = f2add(fv, DUPC(-12582912.0f));
    u64 r2 = f2fma(fm, DUPC(-1.0f), t2);                    // frac in [-0.5,0.5]
    u64 p2 = f2fma(r2, f2fma(r2, f2fma(r2, f2fma(r2, f2fma(r2,
                DUPC(0.0013333558f), DUPC(0.0096181291f)), DUPC(0.0555041087f)),
                DUPC(0.2402265070f)), DUPC(0.6931471806f)), DUPC(1.0f));
    float flo, fhi; upk(flo, fhi, fv);
    float slo = __int_as_float((__float_as_int(flo) << 23) + 0x3F800000);
    float shi = __int_as_float((__float_as_int(fhi) << 23) + 0x3F800000);
    u64 e2 = f2mul(p2, pk(slo, shi));                       // e^{-x^2}
    u64 d2 = f2fma(u2 & 0x7FFFFFFF7FFFFFFFULL, DUPC(0.23164190f), DUPC(1.0f));
    float dlo, dhi; upk(dlo, dhi, d2);
    u64 k2 = pk(__int_as_float(0x7EF311C3 - __float_as_int(dlo)),
                __int_as_float(0x7EF311C3 - __float_as_int(dhi)));
    u64 nd2 = f2mul(d2, DUPC(-1.0f));
    k2 = f2mul(k2, f2fma(nd2, k2, DUPC(2.0f)));
    k2 = f2mul(k2, f2fma(nd2, k2, DUPC(2.0f)));             // 1/(1+0.3275911*x)
    u64 poly = f2mul(k2, f2fma(k2, f2fma(k2, f2fma(k2, f2fma(k2,
                DUPC(0.5307027145f), DUPC(-0.7265760135f)), DUPC(0.7107068705f)),
                DUPC(-0.142248368f)), DUPC(0.127414796f)));
    u64 s2  = f2mul(poly, e2);                              // 0.5*erfc(x) in (0,0.5]
    u64 hs  = f2fma(s2, DUPC(-1.0f), DUPC(0.5f));           // 0.5-s  (>0)
    u64 phi = f2add(hs | (u2 & 0x8000000080000000ULL), DUPC(0.5f));
    return f2mul(u2, phi);
}

// =================== Kernel 1: front, f32x2 (2 adjacent tokens/thread) ===================
__global__ void __launch_bounds__(256, 4)
front_kernel(const float* __restrict__ x) {
    __shared__ u64 sW1d[HID*DIM];        // dup(w,w), layout [j][c]: 6144 B

    const int tid = threadIdx.x;
    for (int i = tid; i < HID*DIM; i += 256) {
        int j = i / DIM, c = i % DIM;
        float w = cW1[c*HID + j];
        sW1d[i] = pk(w, w);
    }
    __syncthreads();

    const size_t tok0 = ((size_t)blockIdx.x * 256 + tid) * 2;   // even token index
    const float4* xp = (const float4*)(x + tok0 * DIM);

    u64 acc2[HID];
    #pragma unroll
    for (int j = 0; j < HID; j++) { float bj = cB1[j]; acc2[j] = pk(bj, bj); }

    #pragma unroll
    for (int c4 = 0; c4 < DIM/4; c4++) {
        float4 a = xp[c4];              // token0 chans c4*4..+3
        float4 c = xp[DIM/4 + c4];      // token1
        u64 xv0 = pk(a.x, c.x), xv1 = pk(a.y, c.y);
        u64 xv2 = pk(a.z, c.z), xv3 = pk(a.w, c.w);
        #pragma unroll
        for (int j = 0; j < HID; j++) {
            const u64* wp = &sW1d[j*DIM + c4*4];     // 16B-aligned (index even)
            ulonglong2 wA = *(const ulonglong2*)wp;
            ulonglong2 wB = *(const ulonglong2*)(wp + 2);
            u64 s = acc2[j];
            s = f2fma(xv0, wA.x, s);
            s = f2fma(xv1, wA.y, s);
            s = f2fma(xv2, wB.x, s);
            s = f2fma(xv3, wB.y, s);
            acc2[j] = s;
        }
    }

    #pragma unroll
    for (int j = 0; j < HID; j++) acc2[j] = gelu2(gelu2(acc2[j]));

    // ---- x1 half -> token-major scratch (64B contiguous for the pair) ----
    {
        float lo[CH], hi[CH];
        #pragma unroll
        for (int j = 0; j < CH; j++) upk(lo[j], hi[j], acc2[j]);
        float4* x1p = (float4*)(g_x1 + tok0 * CH);
        x1p[0] = make_float4(lo[0], lo[1], lo[2], lo[3]);
        x1p[1] = make_float4(lo[4], lo[5], lo[6], lo[7]);
        x1p[2] = make_float4(hi[0], hi[1], hi[2], hi[3]);
        x1p[3] = make_float4(hi[4], hi[5], hi[6], hi[7]);
    }

    // ---- packed layernorm over acc2[8..16) ----
    u64 m2 = acc2[CH];
    #pragma unroll
    for (int j = 1; j < CH; j++) m2 = f2add(m2, acc2[CH + j]);
    m2 = f2mul(m2, DUPC(0.125f));
    u64 d2[CH]; u64 v2 = 0ULL;
    #pragma unroll
    for (int j = 0; j < CH; j++) {
        d2[j] = f2fma(m2, DUPC(-1.0f), acc2[CH + j]);
        v2 = f2fma(d2[j], d2[j], v2);
    }
    v2 = f2fma(v2, DUPC(0.125f), DUPC(1e-5f));
    float vlo, vhi; upk(vlo, vhi, v2);
    u64 is2 = pk(rsqrtf(vlo), rsqrtf(vhi));

    // packed pair (token0, token1) IS the adjacent-pixel store layout for g_n
    const size_t b  = tok0 >> 16;
    const size_t p0 = tok0 & (HW - 1);
    #pragma unroll
    for (int j = 0; j < CH; j++) {
        u64 gm = pk(cGamma[j], cGamma[j]);
        u64 bt = pk(cBeta[j],  cBeta[j]);
        u64 n2 = f2fma(f2mul(d2[j], is2), gm, bt);
        *(u64*)(g_n + ((b*CH + j) << 16) + p0) = n2;     // 8B-aligned (p0 even)
    }
}

// =================== Kernel 2: conv + gate + back GEMM (unchanged) ===================
__global__ void __launch_bounds__(256, 4)
back_kernel(float* __restrict__ out) {
    __shared__ float n_s[CH][HT*PITCH];   // 38080 B
    __shared__ float sW2t[DIM*CH];        // transposed W2: [DIM][CH]

    const int b   = blockIdx.z;
    const int bx  = blockIdx.x * TILE;
    const int by  = blockIdx.y * TILE;
    const int tid = threadIdx.x;
    const int iy  = tid >> 3;            // 0..31
    const int ix1 = (tid & 7) << 2;      // 0,4,...,28 (4 px per thread)
    const int gy  = by + iy;
    const int gx0 = bx + ix1;

    for (int i = tid; i < DIM*CH; i += 256) {
        int o = i >> 3, j = i & 7;
        sW2t[i] = cW2[j*DIM + o];
    }

    // ---- load n tile + halo from global (L2-resident) ----
    const float* nb = g_n + ((size_t)b*CH << 16);
    for (int i = tid; i < CH*HT*HT; i += 256) {
        int c  = i / (HT*HT);
        int r  = i % (HT*HT);
        int hy = r / HT, hx = r % HT;
        int gy2 = by + hy - 1, gx2 = bx + hx - 1;
        float v = 0.f;
        if (gy2 >= 0 && gy2 < HH && gx2 >= 0 && gx2 < WW)
            v = nb[((size_t)c << 16) + gy2*WW + gx2];
        n_s[c][hy*PITCH + hx] = v;
    }
    __syncthreads();

    // ---- x1 for this thread's 4 pixels ----
    float g[4][CH];
    {
        const float4* x1p = (const float4*)(g_x1 + (((size_t)b << 16) + gy*WW + gx0) * CH);
        #pragma unroll
        for (int p = 0; p < 4; p++) {
            float4 a = x1p[2*p], c = x1p[2*p+1];
            g[p][0]=a.x; g[p][1]=a.y; g[p][2]=a.z; g[p][3]=a.w;
            g[p][4]=c.x; g[p][5]=c.y; g[p][6]=c.z; g[p][7]=c.w;
        }
    }

    // ---- dw-conv 3x3 + pw-conv 1x1 + gate ----
    #pragma unroll
    for (int p = 0; p < 4; p++) {
        const int base = (iy+1)*PITCH + (ix1+p+1);
        float nc[CH], sp[CH];
        #pragma unroll
        for (int c = 0; c < CH; c++) {
            nc[c] = n_s[c][base];
            float s = cDWB[c];
            #pragma unroll
            for (int dy = 0; dy < 3; dy++) {
                #pragma unroll
                for (int dx = 0; dx < 3; dx++) {
                    s = fmaf(cDW[c*9 + dy*3 + dx],
                             n_s[c][base + (dy-1)*PITCH + (dx-1)], s);
                }
            }
            sp[c] = s;
        }
        #pragma unroll
        for (int c = 0; c < CH; c++) {
            float t = cPWB[c];
            #pragma unroll
            for (int k = 0; k < CH; k++) t = fmaf(cPW[c*CH + k], nc[k], t);
            g[p][c] *= sp[c] * t;        // g = x1 * (sp * ch)
        }
    }

    // ---- back GEMM g[8] @ W2[8x48] + b2, float4 stores per channel plane ----
    float* outb = out + ((size_t)b*DIM*HH + gy)*WW + gx0;
    #pragma unroll
    for (int o = 0; o < DIM; o++) {
        float4 wa = *(const float4*)&sW2t[o*CH];
        float4 wb = *(const float4*)&sW2t[o*CH + 4];
        float bo = cB2[o];
        float vv[4];
        #pragma unroll
        for (int p = 0; p < 4; p++) {
            float s = bo;
            s = fmaf(g[p][0], wa.x, s);
            s = fmaf(g[p][1], wa.y, s);
            s = fmaf(g[p][2], wa.z, s);
            s = fmaf(g[p][3], wa.w, s);
            s = fmaf(g[p][4], wb.x, s);
            s = fmaf(g[p][5], wb.y, s);
            s = fmaf(g[p][6], wb.z, s);
            s = fmaf(g[p][7], wb.w, s);
            vv[p] = s;
        }
        *(float4*)(outb + (size_t)o*HW) = make_float4(vv[0], vv[1], vv[2], vv[3]);
    }
}

extern "C" void kernel_launch(void* const* d_in, const int* in_sizes, int n_in,
                              void* d_out, int out_size) {
    cudaMemcpyToSymbolAsync(cW1,    d_in[1],  sizeof(cW1),    0, cudaMemcpyDeviceToDevice, 0);
    cudaMemcpyToSymbolAsync(cB1,    d_in[2],  sizeof(cB1),    0, cudaMemcpyDeviceToDevice, 0);
    cudaMemcpyToSymbolAsync(cGamma, d_in[3],  sizeof(cGamma), 0, cudaMemcpyDeviceToDevice, 0);
    cudaMemcpyToSymbolAsync(cBeta,  d_in[4],  sizeof(cBeta),  0, cudaMemcpyDeviceToDevice, 0);
    cudaMemcpyToSymbolAsync(cDW,    d_in[5],  sizeof(cDW),    0, cudaMemcpyDeviceToDevice, 0);
    cudaMemcpyToSymbolAsync(cDWB,   d_in[6],  sizeof(cDWB),   0, cudaMemcpyDeviceToDevice, 0);
    cudaMemcpyToSymbolAsync(cPW,    d_in[7],  sizeof(cPW),    0, cudaMemcpyDeviceToDevice, 0);
    cudaMemcpyToSymbolAsync(cPWB,   d_in[8],  sizeof(cPWB),   0, cudaMemcpyDeviceToDevice, 0);
    cudaMemcpyToSymbolAsync(cW2,    d_in[9],  sizeof(cW2),    0, cudaMemcpyDeviceToDevice, 0);
    cudaMemcpyToSymbolAsync(cB2,    d_in[10], sizeof(cB2),    0, cudaMemcpyDeviceToDevice, 0);

    const float* x = (const float*)d_in[0];
    float* out = (float*)d_out;

    front_kernel<<<BATCH*HW/512, 256>>>(x);                 // 2048 blocks, 2 tokens/thread
    dim3 grid2(WW/TILE, HH/TILE, BATCH);                    // (8, 8, 16)
    back_kernel<<<grid2, 256>>>(out);
}